// round 1
// baseline (speedup 1.0000x reference)
#include <cuda_runtime.h>
#include <math.h>

#define BB 32
#define NN 1024
#define CC 512
#define DD 768
#define EPS 1e-6f

// ---------------- scratch (device globals; no allocations allowed) ----------
__device__ float d_tn[CC * DD];                 // normalized t          (1.5 MB)
__device__ float d_gn[BB * DD];                 // normalized g          (96 KB)
__device__ float d_rnp[BB * NN];                // 1/max(||p_row||,eps)  (128 KB)
__device__ float d_m[(size_t)BB * NN * CC];     // logits / softmax      (64 MB)

// ---------------- block reduction -------------------------------------------
__device__ __forceinline__ float block_reduce_sum(float v) {
    __shared__ float sh[8];
    int lane = threadIdx.x & 31, w = threadIdx.x >> 5;
#pragma unroll
    for (int o = 16; o; o >>= 1) v += __shfl_xor_sync(0xffffffffu, v, o);
    if (!lane) sh[w] = v;
    __syncthreads();
    if (w == 0) {
        float x = (lane < ((int)blockDim.x + 31) / 32) ? sh[lane] : 0.f;
#pragma unroll
        for (int o = 4; o; o >>= 1) x += __shfl_xor_sync(0xffffffffu, x, o);
        if (!lane) sh[0] = x;
    }
    __syncthreads();
    return sh[0];
}

// ---------------- normalization kernels (192 threads = 768 floats/row) ------
__global__ void norm_t_kernel(const float* __restrict__ t) {
    int row = blockIdx.x;
    int i = threadIdx.x * 4;
    float4 v = *(const float4*)(t + (size_t)row * DD + i);
    float ss = v.x * v.x + v.y * v.y + v.z * v.z + v.w * v.w;
    ss = block_reduce_sum(ss);
    float s = 1.f / fmaxf(sqrtf(ss), EPS);
    float4 o = make_float4(v.x * s, v.y * s, v.z * s, v.w * s);
    *(float4*)(d_tn + (size_t)row * DD + i) = o;
}

__global__ void norm_g_kernel(const float* __restrict__ g) {
    int row = blockIdx.x;
    int i = threadIdx.x * 4;
    float4 v = *(const float4*)(g + (size_t)row * DD + i);
    float ss = v.x * v.x + v.y * v.y + v.z * v.z + v.w * v.w;
    ss = block_reduce_sum(ss);
    float s = 1.f / fmaxf(sqrtf(ss), EPS);
    float4 o = make_float4(v.x * s, v.y * s, v.z * s, v.w * s);
    *(float4*)(d_gn + (size_t)row * DD + i) = o;
}

__global__ void pnorm_kernel(const float* __restrict__ p) {
    int row = blockIdx.x;  // 0 .. B*N-1
    float4 v = *(const float4*)(p + (size_t)row * DD + threadIdx.x * 4);
    float ss = v.x * v.x + v.y * v.y + v.z * v.z + v.w * v.w;
    ss = block_reduce_sum(ss);
    if (threadIdx.x == 0) d_rnp[row] = 1.f / fmaxf(sqrtf(ss), EPS);
}

// ---------------- GEMM1: m[b] = diag(rnp) * (p[b] .* gn[b]) @ tn^T ----------
// A: p[b] [N,D] row-major (K contiguous), B: tn [C,D] row-major (K contiguous)
// 128x128 tile, K-step 8, 256 threads, 8x8 per-thread.
__global__ __launch_bounds__(256) void gemm1_kernel(const float* __restrict__ p) {
    int b = blockIdx.z;
    int cTile = blockIdx.x * 128;
    int nTile = blockIdx.y * 128;

    __shared__ __align__(16) float As[8][132];
    __shared__ __align__(16) float Bs[8][132];

    const float* A = p + (size_t)b * NN * DD;
    const float* G = d_gn + (size_t)b * DD;

    int t = threadIdx.x;
    int lrow = t >> 1;          // 0..127
    int kg = (t & 1) * 4;       // 0 or 4
    int tx = t & 15, ty = t >> 4;

    float acc[8][8];
#pragma unroll
    for (int i = 0; i < 8; i++)
#pragma unroll
        for (int j = 0; j < 8; j++) acc[i][j] = 0.f;

    for (int k0 = 0; k0 < DD; k0 += 8) {
        float4 av = *(const float4*)(A + (size_t)(nTile + lrow) * DD + k0 + kg);
        float4 gv = *(const float4*)(G + k0 + kg);
        float4 bv = *(const float4*)(d_tn + (size_t)(cTile + lrow) * DD + k0 + kg);
        As[kg + 0][lrow] = av.x * gv.x;
        As[kg + 1][lrow] = av.y * gv.y;
        As[kg + 2][lrow] = av.z * gv.z;
        As[kg + 3][lrow] = av.w * gv.w;
        Bs[kg + 0][lrow] = bv.x;
        Bs[kg + 1][lrow] = bv.y;
        Bs[kg + 2][lrow] = bv.z;
        Bs[kg + 3][lrow] = bv.w;
        __syncthreads();
#pragma unroll
        for (int kk = 0; kk < 8; kk++) {
            float4 a0 = *(const float4*)&As[kk][ty * 4];
            float4 a1 = *(const float4*)&As[kk][ty * 4 + 64];
            float4 b0 = *(const float4*)&Bs[kk][tx * 4];
            float4 b1 = *(const float4*)&Bs[kk][tx * 4 + 64];
            float ar[8] = {a0.x, a0.y, a0.z, a0.w, a1.x, a1.y, a1.z, a1.w};
            float br[8] = {b0.x, b0.y, b0.z, b0.w, b1.x, b1.y, b1.z, b1.w};
#pragma unroll
            for (int i = 0; i < 8; i++)
#pragma unroll
                for (int j = 0; j < 8; j++) acc[i][j] += ar[i] * br[j];
        }
        __syncthreads();
    }

#pragma unroll
    for (int i = 0; i < 8; i++) {
        int r = nTile + ty * 4 + (i < 4 ? i : i + 60);
        float sc = d_rnp[b * NN + r];
        float4 v0 = make_float4(acc[i][0] * sc, acc[i][1] * sc, acc[i][2] * sc, acc[i][3] * sc);
        float4 v1 = make_float4(acc[i][4] * sc, acc[i][5] * sc, acc[i][6] * sc, acc[i][7] * sc);
        size_t rowbase = ((size_t)b * NN + r) * CC + cTile;
        *(float4*)(d_m + rowbase + tx * 4) = v0;
        *(float4*)(d_m + rowbase + tx * 4 + 64) = v1;
    }
}

// ---------------- softmax over n (axis=1) for each (b,c) --------------------
// grid (B, C/64), 256 threads: 64 columns x 4 n-partitions of 256 each.
__global__ __launch_bounds__(256) void softmax_kernel() {
    int b = blockIdx.x;
    int cx = threadIdx.x & 63;
    int part = threadIdx.x >> 6;  // 0..3
    int c = blockIdx.y * 64 + cx;
    float* base = d_m + (size_t)b * NN * CC;
    int n0 = part * 256, n1 = n0 + 256;

    __shared__ float sred[4][64];

    float mx = -1e30f;
    for (int n = n0; n < n1; n++) mx = fmaxf(mx, base[(size_t)n * CC + c]);
    sred[part][cx] = mx;
    __syncthreads();
    mx = fmaxf(fmaxf(sred[0][cx], sred[1][cx]), fmaxf(sred[2][cx], sred[3][cx]));
    __syncthreads();

    float s = 0.f;
    for (int n = n0; n < n1; n++) s += __expf(base[(size_t)n * CC + c] - mx);
    sred[part][cx] = s;
    __syncthreads();
    s = sred[0][cx] + sred[1][cx] + sred[2][cx] + sred[3][cx];

    float inv = 1.f / s;
    for (int n = n0; n < n1; n++) {
        size_t idx = (size_t)n * CC + c;
        base[idx] = __expf(base[idx] - mx) * inv;
    }
}

// ---------------- GEMM2: out[b] = m[b]^T @ h --------------------------------
// out[b,c,d] = sum_n m[b,n,c] * h[n,d]. Both operands have K (=n) as row dim,
// so K-step tiles load directly into [k][col] smem with float4, no transpose.
__global__ __launch_bounds__(256) void gemm2_kernel(const float* __restrict__ h,
                                                    float* __restrict__ out) {
    int b = blockIdx.z;
    int dTile = blockIdx.x * 128;
    int cTile = blockIdx.y * 128;

    __shared__ __align__(16) float Ms[8][128];
    __shared__ __align__(16) float Hs[8][128];

    int t = threadIdx.x;
    int kk = t >> 5;            // 0..7
    int col = (t & 31) * 4;     // 0..124
    int tx = t & 15, ty = t >> 4;

    float acc[8][8];
#pragma unroll
    for (int i = 0; i < 8; i++)
#pragma unroll
        for (int j = 0; j < 8; j++) acc[i][j] = 0.f;

    const float* M = d_m + (size_t)b * NN * CC;

    for (int k0 = 0; k0 < NN; k0 += 8) {
        float4 mv = *(const float4*)(M + (size_t)(k0 + kk) * CC + cTile + col);
        float4 hv = *(const float4*)(h + (size_t)(k0 + kk) * DD + dTile + col);
        *(float4*)&Ms[kk][col] = mv;
        *(float4*)&Hs[kk][col] = hv;
        __syncthreads();
#pragma unroll
        for (int k = 0; k < 8; k++) {
            float4 a0 = *(const float4*)&Ms[k][ty * 4];
            float4 a1 = *(const float4*)&Ms[k][ty * 4 + 64];
            float4 b0 = *(const float4*)&Hs[k][tx * 4];
            float4 b1 = *(const float4*)&Hs[k][tx * 4 + 64];
            float ar[8] = {a0.x, a0.y, a0.z, a0.w, a1.x, a1.y, a1.z, a1.w};
            float br[8] = {b0.x, b0.y, b0.z, b0.w, b1.x, b1.y, b1.z, b1.w};
#pragma unroll
            for (int i = 0; i < 8; i++)
#pragma unroll
                for (int j = 0; j < 8; j++) acc[i][j] += ar[i] * br[j];
        }
        __syncthreads();
    }

#pragma unroll
    for (int i = 0; i < 8; i++) {
        int c = cTile + ty * 4 + (i < 4 ? i : i + 60);
        size_t rowbase = ((size_t)b * CC + c) * DD + dTile;
        float4 v0 = make_float4(acc[i][0], acc[i][1], acc[i][2], acc[i][3]);
        float4 v1 = make_float4(acc[i][4], acc[i][5], acc[i][6], acc[i][7]);
        *(float4*)(out + rowbase + tx * 4) = v0;
        *(float4*)(out + rowbase + tx * 4 + 64) = v1;
    }
}

// ---------------- launch -----------------------------------------------------
extern "C" void kernel_launch(void* const* d_in, const int* in_sizes, int n_in,
                              void* d_out, int out_size) {
    const float* p = (const float*)d_in[0];
    const float* t = (const float*)d_in[1];
    const float* g = (const float*)d_in[2];
    const float* h = (const float*)d_in[3];
    float* out = (float*)d_out;

    norm_t_kernel<<<CC, 192>>>(t);
    norm_g_kernel<<<BB, 192>>>(g);
    pnorm_kernel<<<BB * NN, 192>>>(p);

    gemm1_kernel<<<dim3(CC / 128, NN / 128, BB), 256>>>(p);
    softmax_kernel<<<dim3(BB, CC / 64), 256>>>();
    gemm2_kernel<<<dim3(DD / 128, CC / 128, BB), 256>>>(h, out);
}

// round 4
// speedup vs baseline: 2.9442x; 2.9442x over previous
#include <cuda_runtime.h>
#include <math.h>
#include <stdint.h>

#define BB 32
#define NN 1024
#define CC 512
#define DD 768
#define EPS 1e-6f

// ---------------- scratch (static device globals) ----------------------------
__device__ float d_tn[CC * DD];                  // normalized t (fp32)
__device__ float d_gn[BB * DD];                  // normalized g (fp32)
__device__ float d_rnp[BB * NN];                 // 1/max(||p_row||,eps)
__device__ float d_p32[(size_t)BB * NN * DD];    // tf32-rounded p      (96MB)
__device__ float d_tng[(size_t)BB * CC * DD];    // tf32(tn*gn) per b   (48MB)
__device__ float d_h32[NN * DD];                 // tf32-rounded h
__device__ float d_m[(size_t)BB * NN * CC];      // logits -> probs     (64MB)

// ---------------- helpers ----------------------------------------------------
__device__ __forceinline__ uint32_t smem_u32(const void* p) {
    uint32_t a;
    asm("{ .reg .u64 t; cvta.to.shared.u64 t, %1; cvt.u32.u64 %0, t; }" : "=r"(a) : "l"(p));
    return a;
}
__device__ __forceinline__ float tf32r(float x) {
    uint32_t r;
    asm("cvt.rna.tf32.f32 %0, %1;" : "=r"(r) : "f"(x));
    return __uint_as_float(r);
}
__device__ __forceinline__ void cp16(uint32_t dst, const void* src) {
    asm volatile("cp.async.cg.shared.global [%0], [%1], 16;" :: "r"(dst), "l"(src));
}
#define CP_COMMIT() asm volatile("cp.async.commit_group;" ::: "memory")
#define CP_WAIT1()  asm volatile("cp.async.wait_group 1;" ::: "memory")
#define CP_WAIT0()  asm volatile("cp.async.wait_group 0;" ::: "memory")

__device__ __forceinline__ void mma_tf32(float* c, const uint32_t* a, const uint32_t* b) {
    asm volatile(
        "mma.sync.aligned.m16n8k8.row.col.f32.tf32.tf32.f32 "
        "{%0,%1,%2,%3}, {%4,%5,%6,%7}, {%8,%9}, {%0,%1,%2,%3};"
        : "+f"(c[0]), "+f"(c[1]), "+f"(c[2]), "+f"(c[3])
        : "r"(a[0]), "r"(a[1]), "r"(a[2]), "r"(a[3]), "r"(b[0]), "r"(b[1]));
}

__device__ __forceinline__ float block_reduce_sum(float v) {
    __shared__ float sh[8];
    int lane = threadIdx.x & 31, w = threadIdx.x >> 5;
#pragma unroll
    for (int o = 16; o; o >>= 1) v += __shfl_xor_sync(0xffffffffu, v, o);
    if (!lane) sh[w] = v;
    __syncthreads();
    if (w == 0) {
        float x = (lane < ((int)blockDim.x + 31) / 32) ? sh[lane] : 0.f;
#pragma unroll
        for (int o = 4; o; o >>= 1) x += __shfl_xor_sync(0xffffffffu, x, o);
        if (!lane) sh[0] = x;
    }
    __syncthreads();
    float r = sh[0];
    __syncthreads();
    return r;
}

// ---------------- prologue kernels -------------------------------------------
__global__ void norm_t_kernel(const float* __restrict__ t) {
    int row = blockIdx.x;
    int i = threadIdx.x * 4;
    float4 v = *(const float4*)(t + (size_t)row * DD + i);
    float ss = block_reduce_sum(v.x * v.x + v.y * v.y + v.z * v.z + v.w * v.w);
    float s = 1.f / fmaxf(sqrtf(ss), EPS);
    *(float4*)(d_tn + (size_t)row * DD + i) = make_float4(v.x * s, v.y * s, v.z * s, v.w * s);
}

__global__ void norm_g_kernel(const float* __restrict__ g) {
    int row = blockIdx.x;
    int i = threadIdx.x * 4;
    float4 v = *(const float4*)(g + (size_t)row * DD + i);
    float ss = block_reduce_sum(v.x * v.x + v.y * v.y + v.z * v.z + v.w * v.w);
    float s = 1.f / fmaxf(sqrtf(ss), EPS);
    *(float4*)(d_gn + (size_t)row * DD + i) = make_float4(v.x * s, v.y * s, v.z * s, v.w * s);
}

// rnp + tf32-rounded p in one pass over p
__global__ void pnorm_kernel(const float* __restrict__ p) {
    int row = blockIdx.x;  // 0..B*N-1
    int i = threadIdx.x * 4;
    float4 v = *(const float4*)(p + (size_t)row * DD + i);
    float ss = block_reduce_sum(v.x * v.x + v.y * v.y + v.z * v.z + v.w * v.w);
    if (threadIdx.x == 0) d_rnp[row] = 1.f / fmaxf(sqrtf(ss), EPS);
    *(float4*)(d_p32 + (size_t)row * DD + i) =
        make_float4(tf32r(v.x), tf32r(v.y), tf32r(v.z), tf32r(v.w));
}

// gated B operand: tng[b][c][d] = tf32(tn[c][d] * gn[b][d])
__global__ void tng_kernel() {
    int c = blockIdx.x, b = blockIdx.y;
    int i = threadIdx.x * 4;
    float4 t = *(const float4*)(d_tn + (size_t)c * DD + i);
    float4 g = *(const float4*)(d_gn + (size_t)b * DD + i);
    *(float4*)(d_tng + ((size_t)b * CC + c) * DD + i) =
        make_float4(tf32r(t.x * g.x), tf32r(t.y * g.y), tf32r(t.z * g.z), tf32r(t.w * g.w));
}

__global__ void h32_kernel(const float* __restrict__ h) {
    int row = blockIdx.x;
    int i = threadIdx.x * 4;
    float4 v = *(const float4*)(h + (size_t)row * DD + i);
    *(float4*)(d_h32 + (size_t)row * DD + i) =
        make_float4(tf32r(v.x), tf32r(v.y), tf32r(v.z), tf32r(v.w));
}

// ---------------- GEMM1: m[b][n][c] = rnp[n] * p32[n,:] . tng[b][c][:] -------
// K = d (768). smem layout: [row][k] stride 36 (pad 4), cp.async-friendly
// (global is k-contiguous) and fragment-LDS conflict-free (bank = 4*row + k).
#define G1_STRIDE 36
#define G1_BUF (128 * G1_STRIDE)            // floats per operand buffer
#define G1_SMEM (4 * G1_BUF * 4)            // bytes: 2 bufs x 2 operands

__global__ __launch_bounds__(256, 2) void gemm1_kernel() {
    extern __shared__ float sm[];
    int tid = threadIdx.x;
    int wid = tid >> 5, lane = tid & 31;
    int b = blockIdx.z;
    int nTile = blockIdx.x * 128;
    int cTile = blockIdx.y * 128;

    const float* Ag = d_p32 + ((size_t)b * NN + nTile) * DD;
    const float* Bg = d_tng + ((size_t)b * CC + cTile) * DD;

    uint32_t smb = smem_u32(sm);
    int srow = tid >> 3;            // 0..31
    int skq = (tid & 7) << 2;       // 0,4,..,28

    float acc[4][4][4];
#pragma unroll
    for (int mi = 0; mi < 4; mi++)
#pragma unroll
        for (int ni = 0; ni < 4; ni++)
#pragma unroll
            for (int q = 0; q < 4; q++) acc[mi][ni][q] = 0.f;

    int warpM = (wid & 1) * 64;
    int warpN = (wid >> 1) * 32;

    const int NCH = DD / 32;  // 24

    // stage chunk 0 into buf 0
    {
        uint32_t aB = smb;
        uint32_t bB = smb + G1_BUF * 4;
#pragma unroll
        for (int j = 0; j < 4; j++) {
            int r = srow + 32 * j;
            uint32_t so = (uint32_t)(r * G1_STRIDE + skq) * 4;
            cp16(aB + so, Ag + (size_t)r * DD + skq);
            cp16(bB + so, Bg + (size_t)r * DD + skq);
        }
    }
    CP_COMMIT();

    for (int i = 0; i < NCH; i++) {
        if (i + 1 < NCH) {
            int nb = (i + 1) & 1;
            int k0 = (i + 1) * 32;
            uint32_t aB = smb + (uint32_t)(nb * 2 * G1_BUF) * 4;
            uint32_t bB = aB + G1_BUF * 4;
#pragma unroll
            for (int j = 0; j < 4; j++) {
                int r = srow + 32 * j;
                uint32_t so = (uint32_t)(r * G1_STRIDE + skq) * 4;
                cp16(aB + so, Ag + (size_t)r * DD + k0 + skq);
                cp16(bB + so, Bg + (size_t)r * DD + k0 + skq);
            }
            CP_COMMIT();
            CP_WAIT1();
        } else {
            CP_WAIT0();
        }
        __syncthreads();

        const float* A = sm + (i & 1) * 2 * G1_BUF;
        const float* B = A + G1_BUF;
#pragma unroll
        for (int kk = 0; kk < 32; kk += 8) {
            uint32_t af[4][4], bf[4][2];
#pragma unroll
            for (int mi = 0; mi < 4; mi++) {
                int r = warpM + mi * 16 + (lane >> 2);
                int k = kk + (lane & 3);
                af[mi][0] = *(const uint32_t*)&A[r * G1_STRIDE + k];
                af[mi][1] = *(const uint32_t*)&A[(r + 8) * G1_STRIDE + k];
                af[mi][2] = *(const uint32_t*)&A[r * G1_STRIDE + k + 4];
                af[mi][3] = *(const uint32_t*)&A[(r + 8) * G1_STRIDE + k + 4];
            }
#pragma unroll
            for (int ni = 0; ni < 4; ni++) {
                int cq = warpN + ni * 8 + (lane >> 2);
                int k = kk + (lane & 3);
                bf[ni][0] = *(const uint32_t*)&B[cq * G1_STRIDE + k];
                bf[ni][1] = *(const uint32_t*)&B[cq * G1_STRIDE + k + 4];
            }
#pragma unroll
            for (int mi = 0; mi < 4; mi++)
#pragma unroll
                for (int ni = 0; ni < 4; ni++) mma_tf32(acc[mi][ni], af[mi], bf[ni]);
        }
        __syncthreads();
    }

    // epilogue: scale rows by rnp, store m[b][n][c]
#pragma unroll
    for (int mi = 0; mi < 4; mi++) {
        int r0 = nTile + warpM + mi * 16 + (lane >> 2);
        int r1 = r0 + 8;
        float s0 = d_rnp[b * NN + r0];
        float s1 = d_rnp[b * NN + r1];
        float* row0 = d_m + ((size_t)b * NN + r0) * CC + cTile;
        float* row1 = d_m + ((size_t)b * NN + r1) * CC + cTile;
#pragma unroll
        for (int ni = 0; ni < 4; ni++) {
            int col = warpN + ni * 8 + (lane & 3) * 2;
            *(float2*)(row0 + col) = make_float2(acc[mi][ni][0] * s0, acc[mi][ni][1] * s0);
            *(float2*)(row1 + col) = make_float2(acc[mi][ni][2] * s1, acc[mi][ni][3] * s1);
        }
    }
}

// ---------------- softmax over n (|logit| <= 1, no max pass needed) ----------
__global__ __launch_bounds__(256) void softmax_kernel() {
    int b = blockIdx.x;
    int cx = threadIdx.x & 63;
    int part = threadIdx.x >> 6;  // 0..3
    int c = blockIdx.y * 64 + cx;
    float* base = d_m + (size_t)b * NN * CC;
    int n0 = part * 256, n1 = n0 + 256;

    __shared__ float sred[4][64];
    float s = 0.f;
    for (int n = n0; n < n1; n++) s += __expf(base[(size_t)n * CC + c]);
    sred[part][cx] = s;
    __syncthreads();
    s = (sred[0][cx] + sred[1][cx]) + (sred[2][cx] + sred[3][cx]);
    float inv = 1.f / s;
    for (int n = n0; n < n1; n++) {
        size_t idx = (size_t)n * CC + c;
        base[idx] = tf32r(__expf(base[idx]) * inv);
    }
}

// ---------------- GEMM2: out[b][c][d] = sum_n m[b][n][c] * h32[n][d] ---------
// K = n (1024). smem layout: [k][col] stride 136, cp.async-friendly
// (global is col-contiguous) and fragment-LDS conflict-free (bank = 8k + col).
#define G2_STRIDE 136
#define G2_BUF (32 * G2_STRIDE)
#define G2_SMEM (4 * G2_BUF * 4)

__global__ __launch_bounds__(256, 2) void gemm2_kernel(float* __restrict__ out) {
    extern __shared__ float sm[];
    int tid = threadIdx.x;
    int wid = tid >> 5, lane = tid & 31;
    int b = blockIdx.z;
    int dTile = blockIdx.x * 128;
    int cTile = blockIdx.y * 128;

    const float* Ag = d_m + (size_t)b * NN * CC + cTile;   // [k=n][c]
    const float* Bg = d_h32 + dTile;                       // [k=n][d]

    uint32_t smb = smem_u32(sm);
    int skk = tid >> 5;            // 0..7
    int sc4 = (tid & 31) << 2;     // 0..124

    float acc[4][4][4];
#pragma unroll
    for (int mi = 0; mi < 4; mi++)
#pragma unroll
        for (int ni = 0; ni < 4; ni++)
#pragma unroll
            for (int q = 0; q < 4; q++) acc[mi][ni][q] = 0.f;

    int warpM = (wid & 1) * 64;   // c
    int warpN = (wid >> 1) * 32;  // d

    const int NCH = NN / 32;  // 32

    {
        uint32_t aB = smb;
        uint32_t bB = smb + G2_BUF * 4;
#pragma unroll
        for (int j = 0; j < 4; j++) {
            int kk = skk + 8 * j;
            uint32_t so = (uint32_t)(kk * G2_STRIDE + sc4) * 4;
            cp16(aB + so, Ag + (size_t)kk * CC + sc4);
            cp16(bB + so, Bg + (size_t)kk * DD + sc4);
        }
    }
    CP_COMMIT();

    for (int i = 0; i < NCH; i++) {
        if (i + 1 < NCH) {
            int nb = (i + 1) & 1;
            int k0 = (i + 1) * 32;
            uint32_t aB = smb + (uint32_t)(nb * 2 * G2_BUF) * 4;
            uint32_t bB = aB + G2_BUF * 4;
#pragma unroll
            for (int j = 0; j < 4; j++) {
                int kk = skk + 8 * j;
                uint32_t so = (uint32_t)(kk * G2_STRIDE + sc4) * 4;
                cp16(aB + so, Ag + (size_t)(k0 + kk) * CC + sc4);
                cp16(bB + so, Bg + (size_t)(k0 + kk) * DD + sc4);
            }
            CP_COMMIT();
            CP_WAIT1();
        } else {
            CP_WAIT0();
        }
        __syncthreads();

        const float* A = sm + (i & 1) * 2 * G2_BUF;
        const float* B = A + G2_BUF;
#pragma unroll
        for (int kk = 0; kk < 32; kk += 8) {
            uint32_t af[4][4], bf[4][2];
#pragma unroll
            for (int mi = 0; mi < 4; mi++) {
                int r = warpM + mi * 16 + (lane >> 2);
                int k = kk + (lane & 3);
                af[mi][0] = *(const uint32_t*)&A[k * G2_STRIDE + r];
                af[mi][1] = *(const uint32_t*)&A[k * G2_STRIDE + r + 8];
                af[mi][2] = *(const uint32_t*)&A[(k + 4) * G2_STRIDE + r];
                af[mi][3] = *(const uint32_t*)&A[(k + 4) * G2_STRIDE + r + 8];
            }
#pragma unroll
            for (int ni = 0; ni < 4; ni++) {
                int cq = warpN + ni * 8 + (lane >> 2);
                int k = kk + (lane & 3);
                bf[ni][0] = *(const uint32_t*)&B[k * G2_STRIDE + cq];
                bf[ni][1] = *(const uint32_t*)&B[(k + 4) * G2_STRIDE + cq];
            }
#pragma unroll
            for (int mi = 0; mi < 4; mi++)
#pragma unroll
                for (int ni = 0; ni < 4; ni++) mma_tf32(acc[mi][ni], af[mi], bf[ni]);
        }
        __syncthreads();
    }

#pragma unroll
    for (int mi = 0; mi < 4; mi++) {
        int c0 = cTile + warpM + mi * 16 + (lane >> 2);
        float* row0 = out + ((size_t)b * CC + c0) * DD + dTile;
        float* row1 = out + ((size_t)b * CC + c0 + 8) * DD + dTile;
#pragma unroll
        for (int ni = 0; ni < 4; ni++) {
            int col = warpN + ni * 8 + (lane & 3) * 2;
            *(float2*)(row0 + col) = make_float2(acc[mi][ni][0], acc[mi][ni][1]);
            *(float2*)(row1 + col) = make_float2(acc[mi][ni][2], acc[mi][ni][3]);
        }
    }
}

// ---------------- launch -----------------------------------------------------
extern "C" void kernel_launch(void* const* d_in, const int* in_sizes, int n_in,
                              void* d_out, int out_size) {
    const float* p = (const float*)d_in[0];
    const float* t = (const float*)d_in[1];
    const float* g = (const float*)d_in[2];
    const float* h = (const float*)d_in[3];
    float* out = (float*)d_out;

    cudaFuncSetAttribute(gemm1_kernel, cudaFuncAttributeMaxDynamicSharedMemorySize, G1_SMEM);
    cudaFuncSetAttribute(gemm2_kernel, cudaFuncAttributeMaxDynamicSharedMemorySize, G2_SMEM);

    norm_t_kernel<<<CC, 192>>>(t);
    norm_g_kernel<<<BB, 192>>>(g);
    pnorm_kernel<<<BB * NN, 192>>>(p);
    tng_kernel<<<dim3(CC, BB), 192>>>();
    h32_kernel<<<NN, 192>>>(h);

    gemm1_kernel<<<dim3(NN / 128, CC / 128, BB), 256, G1_SMEM>>>();
    softmax_kernel<<<dim3(BB, CC / 64), 256>>>();
    gemm2_kernel<<<dim3(DD / 128, CC / 128, BB), 256, G2_SMEM>>>(out);
}

// round 8
// speedup vs baseline: 2.9720x; 1.0094x over previous
#include <cuda_runtime.h>
#include <math.h>
#include <stdint.h>

#define BB 32
#define NN 1024
#define CC 512
#define DD 768
#define EPS 1e-6f

// ---------------- scratch ----------------------------------------------------
__device__ float d_tn[CC * DD];                  // normalized t
__device__ float d_gn[BB * DD];                  // normalized g
__device__ float d_rnp[BB * NN];                 // 1/max(||p_row||,eps)
__device__ float d_h32[NN * DD];                 // tf32-rounded h
__device__ float d_m[(size_t)BB * NN * CC];      // logits -> probs (64MB)

// ---------------- helpers ----------------------------------------------------
__device__ __forceinline__ uint32_t smem_u32(const void* p) {
    uint32_t a;
    asm("{ .reg .u64 t; cvta.to.shared.u64 t, %1; cvt.u32.u64 %0, t; }" : "=r"(a) : "l"(p));
    return a;
}
__device__ __forceinline__ float tf32r(float x) {
    uint32_t r;
    asm("cvt.rna.tf32.f32 %0, %1;" : "=r"(r) : "f"(x));
    return __uint_as_float(r);
}
__device__ __forceinline__ uint32_t tf32u(float x) {
    uint32_t r;
    asm("cvt.rna.tf32.f32 %0, %1;" : "=r"(r) : "f"(x));
    return r;
}
__device__ __forceinline__ void cp16(uint32_t dst, const void* src) {
    asm volatile("cp.async.cg.shared.global [%0], [%1], 16;" :: "r"(dst), "l"(src));
}
#define CP_COMMIT() asm volatile("cp.async.commit_group;" ::: "memory")
#define CP_WAIT1()  asm volatile("cp.async.wait_group 1;" ::: "memory")
#define CP_WAIT0()  asm volatile("cp.async.wait_group 0;" ::: "memory")

__device__ __forceinline__ void mma_tf32(float* c, const uint32_t* a, const uint32_t* b) {
    asm volatile(
        "mma.sync.aligned.m16n8k8.row.col.f32.tf32.tf32.f32 "
        "{%0,%1,%2,%3}, {%4,%5,%6,%7}, {%8,%9}, {%0,%1,%2,%3};"
        : "+f"(c[0]), "+f"(c[1]), "+f"(c[2]), "+f"(c[3])
        : "r"(a[0]), "r"(a[1]), "r"(a[2]), "r"(a[3]), "r"(b[0]), "r"(b[1]));
}

__device__ __forceinline__ float block_reduce_sum(float v) {
    __shared__ float sh[8];
    int lane = threadIdx.x & 31, w = threadIdx.x >> 5;
#pragma unroll
    for (int o = 16; o; o >>= 1) v += __shfl_xor_sync(0xffffffffu, v, o);
    if (!lane) sh[w] = v;
    __syncthreads();
    if (w == 0) {
        float x = (lane < ((int)blockDim.x + 31) / 32) ? sh[lane] : 0.f;
#pragma unroll
        for (int o = 4; o; o >>= 1) x += __shfl_xor_sync(0xffffffffu, x, o);
        if (!lane) sh[0] = x;
    }
    __syncthreads();
    float r = sh[0];
    __syncthreads();
    return r;
}

// ---------------- prologue ---------------------------------------------------
__global__ void norm_t_kernel(const float* __restrict__ t) {
    int row = blockIdx.x;
    int i = threadIdx.x * 4;
    float4 v = *(const float4*)(t + (size_t)row * DD + i);
    float ss = block_reduce_sum(v.x * v.x + v.y * v.y + v.z * v.z + v.w * v.w);
    float s = 1.f / fmaxf(sqrtf(ss), EPS);
    *(float4*)(d_tn + (size_t)row * DD + i) = make_float4(v.x * s, v.y * s, v.z * s, v.w * s);
}

__global__ void norm_g_kernel(const float* __restrict__ g) {
    int row = blockIdx.x;
    int i = threadIdx.x * 4;
    float4 v = *(const float4*)(g + (size_t)row * DD + i);
    float ss = block_reduce_sum(v.x * v.x + v.y * v.y + v.z * v.z + v.w * v.w);
    float s = 1.f / fmaxf(sqrtf(ss), EPS);
    *(float4*)(d_gn + (size_t)row * DD + i) = make_float4(v.x * s, v.y * s, v.z * s, v.w * s);
}

__global__ void pnorm_kernel(const float* __restrict__ p) {
    int row = blockIdx.x;
    float4 v = *(const float4*)(p + (size_t)row * DD + threadIdx.x * 4);
    float ss = block_reduce_sum(v.x * v.x + v.y * v.y + v.z * v.z + v.w * v.w);
    if (threadIdx.x == 0) d_rnp[row] = 1.f / fmaxf(sqrtf(ss), EPS);
}

__global__ void h32_kernel(const float* __restrict__ h) {
    int row = blockIdx.x;
    int i = threadIdx.x * 4;
    float4 v = *(const float4*)(h + (size_t)row * DD + i);
    *(float4*)(d_h32 + (size_t)row * DD + i) =
        make_float4(tf32r(v.x), tf32r(v.y), tf32r(v.z), tf32r(v.w));
}

// ---------------- GEMM1: m[b][n][c] = rnp[n] * p[n,:].(tn[c,:]*gn[b,:]) ------
// A = raw p (tf32 cvt in-register), B = raw tn (gate applied in-register).
// smem: A,B double buffers [row][k] stride 36; g row (768 floats).
#define G1_STRIDE 36
#define G1_BUF (128 * G1_STRIDE)
#define G1_GOFF (4 * G1_BUF)
#define G1_SMEM ((G1_GOFF + DD) * 4)

__global__ __launch_bounds__(256, 2) void gemm1_kernel(const float* __restrict__ p) {
    extern __shared__ float sm[];
    int tid = threadIdx.x;
    int wid = tid >> 5, lane = tid & 31;
    int b = blockIdx.z;
    int nTile = blockIdx.x * 128;
    int cTile = blockIdx.y * 128;

    const float* Ag = p + ((size_t)b * NN + nTile) * DD;
    const float* Bg = d_tn + (size_t)cTile * DD;
    float* sg = sm + G1_GOFF;

    for (int i = tid; i < DD; i += 256) sg[i] = d_gn[(size_t)b * DD + i];

    uint32_t smb = smem_u32(sm);
    int srow = tid >> 3;
    int skq = (tid & 7) << 2;

    float acc[4][4][4];
#pragma unroll
    for (int mi = 0; mi < 4; mi++)
#pragma unroll
        for (int ni = 0; ni < 4; ni++)
#pragma unroll
            for (int q = 0; q < 4; q++) acc[mi][ni][q] = 0.f;

    int warpM = (wid & 1) * 64;
    int warpN = (wid >> 1) * 32;

    const int NCH = DD / 32;  // 24

    {
        uint32_t aB = smb;
        uint32_t bB = smb + G1_BUF * 4;
#pragma unroll
        for (int j = 0; j < 4; j++) {
            int r = srow + 32 * j;
            uint32_t so = (uint32_t)(r * G1_STRIDE + skq) * 4;
            cp16(aB + so, Ag + (size_t)r * DD + skq);
            cp16(bB + so, Bg + (size_t)r * DD + skq);
        }
    }
    CP_COMMIT();

    for (int i = 0; i < NCH; i++) {
        if (i + 1 < NCH) {
            int nb = (i + 1) & 1;
            int k0 = (i + 1) * 32;
            uint32_t aB = smb + (uint32_t)(nb * 2 * G1_BUF) * 4;
            uint32_t bB = aB + G1_BUF * 4;
#pragma unroll
            for (int j = 0; j < 4; j++) {
                int r = srow + 32 * j;
                uint32_t so = (uint32_t)(r * G1_STRIDE + skq) * 4;
                cp16(aB + so, Ag + (size_t)r * DD + k0 + skq);
                cp16(bB + so, Bg + (size_t)r * DD + k0 + skq);
            }
            CP_COMMIT();
            CP_WAIT1();
        } else {
            CP_WAIT0();
        }
        __syncthreads();

        const float* A = sm + (i & 1) * 2 * G1_BUF;
        const float* B = A + G1_BUF;
        int kbase = i * 32;
#pragma unroll
        for (int kk = 0; kk < 32; kk += 8) {
            int k = kk + (lane & 3);
            float g0 = sg[kbase + k];
            float g4 = sg[kbase + k + 4];
            uint32_t af[4][4], bf[4][2];
#pragma unroll
            for (int mi = 0; mi < 4; mi++) {
                int r = warpM + mi * 16 + (lane >> 2);
                af[mi][0] = tf32u(A[r * G1_STRIDE + k]);
                af[mi][1] = tf32u(A[(r + 8) * G1_STRIDE + k]);
                af[mi][2] = tf32u(A[r * G1_STRIDE + k + 4]);
                af[mi][3] = tf32u(A[(r + 8) * G1_STRIDE + k + 4]);
            }
#pragma unroll
            for (int ni = 0; ni < 4; ni++) {
                int cq = warpN + ni * 8 + (lane >> 2);
                bf[ni][0] = tf32u(B[cq * G1_STRIDE + k] * g0);
                bf[ni][1] = tf32u(B[cq * G1_STRIDE + k + 4] * g4);
            }
#pragma unroll
            for (int mi = 0; mi < 4; mi++)
#pragma unroll
                for (int ni = 0; ni < 4; ni++) mma_tf32(acc[mi][ni], af[mi], bf[ni]);
        }
        __syncthreads();
    }

    // epilogue: scale rows by rnp, store logits (R4-style, no fusion)
#pragma unroll
    for (int mi = 0; mi < 4; mi++) {
        int r0 = nTile + warpM + mi * 16 + (lane >> 2);
        int r1 = r0 + 8;
        float s0 = d_rnp[b * NN + r0];
        float s1 = d_rnp[b * NN + r1];
        float* row0 = d_m + ((size_t)b * NN + r0) * CC + cTile;
        float* row1 = d_m + ((size_t)b * NN + r1) * CC + cTile;
#pragma unroll
        for (int ni = 0; ni < 4; ni++) {
            int col = warpN + ni * 8 + (lane & 3) * 2;
            *(float2*)(row0 + col) = make_float2(acc[mi][ni][0] * s0, acc[mi][ni][1] * s0);
            *(float2*)(row1 + col) = make_float2(acc[mi][ni][2] * s1, acc[mi][ni][3] * s1);
        }
    }
}

// ---------------- softmax over n (|logit| <= 1, no max pass needed) ----------
__global__ __launch_bounds__(256) void softmax_kernel() {
    int b = blockIdx.x;
    int cx = threadIdx.x & 63;
    int part = threadIdx.x >> 6;  // 0..3
    int c = blockIdx.y * 64 + cx;
    float* base = d_m + (size_t)b * NN * CC;
    int n0 = part * 256, n1 = n0 + 256;

    __shared__ float sred[4][64];
    float s = 0.f;
    for (int n = n0; n < n1; n++) s += __expf(base[(size_t)n * CC + c]);
    sred[part][cx] = s;
    __syncthreads();
    s = (sred[0][cx] + sred[1][cx]) + (sred[2][cx] + sred[3][cx]);
    float inv = 1.f / s;
    for (int n = n0; n < n1; n++) {
        size_t idx = (size_t)n * CC + c;
        base[idx] = tf32r(__expf(base[idx]) * inv);
    }
}

// ---------------- GEMM2: out[b][c][d] = sum_n m[b][n][c] * h32[n][d] ---------
#define G2_STRIDE 136
#define G2_BUF (32 * G2_STRIDE)
#define G2_SMEM (4 * G2_BUF * 4)

__global__ __launch_bounds__(256, 2) void gemm2_kernel(float* __restrict__ out) {
    extern __shared__ float sm[];
    int tid = threadIdx.x;
    int wid = tid >> 5, lane = tid & 31;
    int b = blockIdx.z;
    int dTile = blockIdx.x * 128;
    int cTile = blockIdx.y * 128;

    const float* Ag = d_m + (size_t)b * NN * CC + cTile;   // [k=n][c]
    const float* Bg = d_h32 + dTile;                       // [k=n][d]

    uint32_t smb = smem_u32(sm);
    int skk = tid >> 5;
    int sc4 = (tid & 31) << 2;

    float acc[4][4][4];
#pragma unroll
    for (int mi = 0; mi < 4; mi++)
#pragma unroll
        for (int ni = 0; ni < 4; ni++)
#pragma unroll
            for (int q = 0; q < 4; q++) acc[mi][ni][q] = 0.f;

    int warpM = (wid & 1) * 64;   // c
    int warpN = (wid >> 1) * 32;  // d

    const int NCH = NN / 32;  // 32

    {
        uint32_t aB = smb;
        uint32_t bB = smb + G2_BUF * 4;
#pragma unroll
        for (int j = 0; j < 4; j++) {
            int kk = skk + 8 * j;
            uint32_t so = (uint32_t)(kk * G2_STRIDE + sc4) * 4;
            cp16(aB + so, Ag + (size_t)kk * CC + sc4);
            cp16(bB + so, Bg + (size_t)kk * DD + sc4);
        }
    }
    CP_COMMIT();

    for (int i = 0; i < NCH; i++) {
        if (i + 1 < NCH) {
            int nb = (i + 1) & 1;
            int k0 = (i + 1) * 32;
            uint32_t aB = smb + (uint32_t)(nb * 2 * G2_BUF) * 4;
            uint32_t bB = aB + G2_BUF * 4;
#pragma unroll
            for (int j = 0; j < 4; j++) {
                int kk = skk + 8 * j;
                uint32_t so = (uint32_t)(kk * G2_STRIDE + sc4) * 4;
                cp16(aB + so, Ag + (size_t)(k0 + kk) * CC + sc4);
                cp16(bB + so, Bg + (size_t)(k0 + kk) * DD + sc4);
            }
            CP_COMMIT();
            CP_WAIT1();
        } else {
            CP_WAIT0();
        }
        __syncthreads();

        const float* A = sm + (i & 1) * 2 * G2_BUF;
        const float* B = A + G2_BUF;
#pragma unroll
        for (int kk = 0; kk < 32; kk += 8) {
            uint32_t af[4][4], bf[4][2];
#pragma unroll
            for (int mi = 0; mi < 4; mi++) {
                int r = warpM + mi * 16 + (lane >> 2);
                int k = kk + (lane & 3);
                af[mi][0] = *(const uint32_t*)&A[k * G2_STRIDE + r];
                af[mi][1] = *(const uint32_t*)&A[k * G2_STRIDE + r + 8];
                af[mi][2] = *(const uint32_t*)&A[(k + 4) * G2_STRIDE + r];
                af[mi][3] = *(const uint32_t*)&A[(k + 4) * G2_STRIDE + r + 8];
            }
#pragma unroll
            for (int ni = 0; ni < 4; ni++) {
                int cq = warpN + ni * 8 + (lane >> 2);
                int k = kk + (lane & 3);
                bf[ni][0] = *(const uint32_t*)&B[k * G2_STRIDE + cq];
                bf[ni][1] = *(const uint32_t*)&B[(k + 4) * G2_STRIDE + cq];
            }
#pragma unroll
            for (int mi = 0; mi < 4; mi++)
#pragma unroll
                for (int ni = 0; ni < 4; ni++) mma_tf32(acc[mi][ni], af[mi], bf[ni]);
        }
        __syncthreads();
    }

#pragma unroll
    for (int mi = 0; mi < 4; mi++) {
        int c0 = cTile + warpM + mi * 16 + (lane >> 2);
        float* row0 = out + ((size_t)b * CC + c0) * DD + dTile;
        float* row1 = out + ((size_t)b * CC + c0 + 8) * DD + dTile;
#pragma unroll
        for (int ni = 0; ni < 4; ni++) {
            int col = warpN + ni * 8 + (lane & 3) * 2;
            *(float2*)(row0 + col) = make_float2(acc[mi][ni][0], acc[mi][ni][1]);
            *(float2*)(row1 + col) = make_float2(acc[mi][ni][2], acc[mi][ni][3]);
        }
    }
}

// ---------------- launch -----------------------------------------------------
extern "C" void kernel_launch(void* const* d_in, const int* in_sizes, int n_in,
                              void* d_out, int out_size) {
    const float* p = (const float*)d_in[0];
    const float* t = (const float*)d_in[1];
    const float* g = (const float*)d_in[2];
    const float* h = (const float*)d_in[3];
    float* out = (float*)d_out;

    cudaFuncSetAttribute(gemm1_kernel, cudaFuncAttributeMaxDynamicSharedMemorySize, G1_SMEM);
    cudaFuncSetAttribute(gemm2_kernel, cudaFuncAttributeMaxDynamicSharedMemorySize, G2_SMEM);

    norm_t_kernel<<<CC, 192>>>(t);
    norm_g_kernel<<<BB, 192>>>(g);
    pnorm_kernel<<<BB * NN, 192>>>(p);
    h32_kernel<<<NN, 192>>>(h);

    gemm1_kernel<<<dim3(NN / 128, CC / 128, BB), 256, G1_SMEM>>>(p);
    softmax_kernel<<<dim3(BB, CC / 64), 256>>>();
    gemm2_kernel<<<dim3(DD / 128, CC / 128, BB), 256, G2_SMEM>>>(out);
}